// round 2
// baseline (speedup 1.0000x reference)
#include <cuda_runtime.h>

// ExactWeightedDTM: B=4, H=W=64, N=4096, R=2, M0=0.01
//
// Key identities:
//  - R=2 => dists_pow == d2 (integer, 0..7938), up to sqrt/square rounding ~1e-7.
//  - Sort order depends only on geometry; counting-sort offsets (dy,dx) by d2.
//  - Tie order within equal d2 does not affect the result (same multiplier,
//    total take = min(group mass, remaining)).
//  - Sequential take = min(w, m_target - accum) over d2-nondecreasing order
//    reproduces the reference clamped-cumsum math exactly.

#define NB      4
#define HH      64
#define WW      64
#define NPIX    4096
#define NBINS   8192      // pow2 >= 7939 distinct d2 bins, for Blelloch scan
#define NOFF    16129     // 127*127 offsets
#define M0F     0.01f

__device__ int   g_offsets[NOFF];   // packed ((dy+63)<<8)|(dx+63), sorted by d2
__device__ float g_mtarget[NB];

// ---------------------------------------------------------------------------
// Kernel 1: build d2-sorted offset table (single block, shared-mem counting sort)
// ---------------------------------------------------------------------------
__global__ void build_table_kernel() {
    __shared__ int s[NBINS];                 // 32 KB
    const int tid = threadIdx.x;
    const int nt  = blockDim.x;              // 1024

    for (int i = tid; i < NBINS; i += nt) s[i] = 0;
    __syncthreads();

    // histogram of d2 over all (dy,dx) in [-63,63]^2
    for (int i = tid; i < NOFF; i += nt) {
        int dy = i / 127 - 63;
        int dx = i % 127 - 63;
        atomicAdd(&s[dy * dy + dx * dx], 1);
    }
    __syncthreads();

    // Blelloch in-place exclusive scan over NBINS
    for (int d = 1; d < NBINS; d <<= 1) {
        int m = NBINS / (2 * d);
        for (int i = tid; i < m; i += nt) {
            int ai = (2 * i + 1) * d - 1;
            int bi = (2 * i + 2) * d - 1;
            s[bi] += s[ai];
        }
        __syncthreads();
    }
    if (tid == 0) s[NBINS - 1] = 0;
    __syncthreads();
    for (int d = NBINS / 2; d >= 1; d >>= 1) {
        int m = NBINS / (2 * d);
        for (int i = tid; i < m; i += nt) {
            int ai = (2 * i + 1) * d - 1;
            int bi = (2 * i + 2) * d - 1;
            int t = s[ai];
            s[ai] = s[bi];
            s[bi] += t;
        }
        __syncthreads();
    }

    // scatter: s[d2] is now the exclusive start of bucket d2; atomic = allocator
    for (int i = tid; i < NOFF; i += nt) {
        int dy = i / 127 - 63;
        int dx = i % 127 - 63;
        int d2 = dy * dy + dx * dx;
        int pos = atomicAdd(&s[d2], 1);
        g_offsets[pos] = ((dy + 63) << 8) | (dx + 63);
    }
}

// ---------------------------------------------------------------------------
// Kernel 2: per-batch total mass -> m_target
// ---------------------------------------------------------------------------
__global__ void mass_kernel(const float* __restrict__ img) {
    __shared__ float red[8];
    const int b = blockIdx.x;
    const float* p = img + b * NPIX;

    float sum = 0.f;
    for (int i = threadIdx.x; i < NPIX; i += 256) sum += p[i];
    #pragma unroll
    for (int o = 16; o; o >>= 1) sum += __shfl_xor_sync(0xFFFFFFFFu, sum, o);
    if ((threadIdx.x & 31) == 0) red[threadIdx.x >> 5] = sum;
    __syncthreads();
    if (threadIdx.x < 32) {
        float v = (threadIdx.x < 8) ? red[threadIdx.x] : 0.f;
        #pragma unroll
        for (int o = 4; o; o >>= 1) v += __shfl_xor_sync(0xFFFFFFFFu, v, o);
        if (threadIdx.x == 0) g_mtarget[b] = M0F * v;
    }
}

// ---------------------------------------------------------------------------
// Kernel 3: DTM per query pixel — walk offsets in d2 order until mass reached
// ---------------------------------------------------------------------------
__global__ void dtm_kernel(const float* __restrict__ img, float* __restrict__ out) {
    const int idx = blockIdx.x * blockDim.x + threadIdx.x;   // 0..16383
    const int b   = idx >> 12;
    const int pix = idx & (NPIX - 1);
    const int y   = pix >> 6;
    const int x   = pix & 63;

    const float mt = g_mtarget[b];
    if (mt <= 0.f) { out[idx] = 0.f; return; }

    const float* p = img + b * NPIX;

    float accum = 0.f;
    float wsum  = 0.f;

    for (int k = 0; k < NOFF; k++) {
        const int pk = g_offsets[k];           // uniform across warp -> 1 req
        const int dy = (pk >> 8) - 63;
        const int dx = (pk & 255) - 63;
        const int ny = y + dy;
        const int nx = x + dx;
        if ((unsigned)ny < (unsigned)HH && (unsigned)nx < (unsigned)WW) {
            const float w    = p[(ny << 6) | nx];   // coalesced across lanes
            const float take = fminf(w, mt - accum);
            wsum  += take * (float)(dy * dy + dx * dx);
            accum += w;
            if (accum >= mt) break;
        }
    }
    out[idx] = sqrtf(wsum / mt);
}

// ---------------------------------------------------------------------------
extern "C" void kernel_launch(void* const* d_in, const int* in_sizes, int n_in,
                              void* d_out, int out_size) {
    const float* img = (const float*)d_in[0];
    float*       out = (float*)d_out;

    build_table_kernel<<<1, 1024>>>();
    mass_kernel<<<NB, 256>>>(img);
    dtm_kernel<<<(NB * NPIX) / 256, 256>>>(img, out);
}

// round 5
// speedup vs baseline: 2.4618x; 2.4618x over previous
#include <cuda_runtime.h>

// ExactWeightedDTM: B=4, H=W=64, N=4096, R=2, M0=0.01
//
// Identities (validated in R1, rel_err 1.3e-7):
//  - R=2 => dists_pow == d2 (integer 0..7938).
//  - Sort order is pure geometry: counting-sort offsets (dy,dx) by d2.
//  - Tie order within equal d2 is irrelevant to the result.
//  - Clamped take = max(min(w, mt - prefix), 0) over d2-nondecreasing order
//    reproduces the reference clamped-cumsum exactly, and is insensitive to
//    processing offsets PAST the stopping point (take clamps to 0).

#define NB        4
#define HH        64
#define WW        64
#define NPIX      4096
#define NBINS     8192      // pow2 >= 7939 d2 bins
#define NOFF      16129     // 127*127 offsets
#define NOFF_PAD  16160     // next multiple of 32; pad entries decode OOB
#define M0F       0.01f
#define FULL      0xFFFFFFFFu

__device__ int   g_offsets[NOFF_PAD];  // packed ((dy+63)<<8)|(dx+63), d2-sorted
__device__ float g_mtarget[NB];

// ---------------------------------------------------------------------------
// Kernel 1: mass reduction + d2-sorted offset table (one block, 1024 threads)
// Scan: per-thread serial (8 bins) -> warp shfl scan -> 1-warp block scan.
// ---------------------------------------------------------------------------
__global__ void build_kernel(const float* __restrict__ img) {
    __shared__ int   s[NBINS];          // 32 KB
    __shared__ int   warpsum[32];
    __shared__ float bmass[NB];

    const int tid  = threadIdx.x;       // 0..1023
    const int lane = tid & 31;
    const int wid  = tid >> 5;

    // ---- per-batch mass (threads 0..255 -> batch0, etc.) ----
    if (tid < NB) bmass[tid] = 0.f;
    for (int i = tid; i < NBINS; i += 1024) s[i] = 0;
    __syncthreads();

    {
        const int b = tid >> 8;                 // 4 batches x 256 threads
        const int t = tid & 255;
        const float* p = img + b * NPIX;
        float sum = 0.f;
        #pragma unroll
        for (int j = 0; j < 16; j++) sum += p[t + j * 256];
        #pragma unroll
        for (int o = 16; o; o >>= 1) sum += __shfl_xor_sync(FULL, sum, o);
        if (lane == 0) atomicAdd(&bmass[b], sum);
    }

    // ---- histogram of d2 over all (dy,dx) in [-63,63]^2 ----
    #pragma unroll
    for (int j = 0; j < 16; j++) {
        int i = tid + j * 1024;
        if (i < NOFF) {
            int dy = i / 127 - 63;
            int dx = i % 127 - 63;
            atomicAdd(&s[dy * dy + dx * dx], 1);
        }
    }
    __syncthreads();

    // ---- exclusive scan of s[0..8191]: 8 bins per thread ----
    const int base = tid * 8;
    int c[8], local[8];
    int run = 0;
    #pragma unroll
    for (int j = 0; j < 8; j++) {
        c[j] = s[base + j];
        run += c[j];
        local[j] = run;                          // inclusive within thread
    }
    int ws = run;                                // warp inclusive scan of run
    #pragma unroll
    for (int o = 1; o < 32; o <<= 1) {
        int t = __shfl_up_sync(FULL, ws, o);
        if (lane >= o) ws += t;
    }
    if (lane == 31) warpsum[wid] = ws;
    __syncthreads();
    if (tid < 32) {
        int t = warpsum[tid];
        int sc = t;
        #pragma unroll
        for (int o = 1; o < 32; o <<= 1) {
            int u = __shfl_up_sync(FULL, sc, o);
            if (tid >= o) sc += u;
        }
        warpsum[tid] = sc - t;                   // exclusive warp prefix
    }
    __syncthreads();
    const int thr_excl = warpsum[wid] + (ws - run);   // exclusive prefix of this thread
    #pragma unroll
    for (int j = 0; j < 8; j++)
        s[base + j] = thr_excl + local[j] - c[j];     // exclusive bin prefix
    __syncthreads();

    // ---- scatter: s[d2] is the bucket allocator ----
    #pragma unroll
    for (int j = 0; j < 16; j++) {
        int i = tid + j * 1024;
        if (i < NOFF) {
            int dy = i / 127 - 63;
            int dx = i % 127 - 63;
            int pos = atomicAdd(&s[dy * dy + dx * dx], 1);
            g_offsets[pos] = ((dy + 63) << 8) | (dx + 63);
        }
    }
    // pad entries decode to dy=+64 -> always OOB
    if (tid < NOFF_PAD - NOFF) g_offsets[NOFF + tid] = 0x7F7F;

    if (tid < NB) g_mtarget[tid] = M0F * bmass[tid];
}

// ---------------------------------------------------------------------------
// Kernel 2: DTM, ONE WARP PER PIXEL. Each step consumes 32 offsets via an
// inclusive warp-scan of weights; clamped take makes overshoot harmless.
// ---------------------------------------------------------------------------
__global__ void dtm_kernel(const float* __restrict__ img, float* __restrict__ out) {
    const int gwarp = (blockIdx.x * blockDim.x + threadIdx.x) >> 5;  // 0..16383
    const int lane  = threadIdx.x & 31;
    const int b     = gwarp >> 12;
    const int pix   = gwarp & (NPIX - 1);
    const int y     = pix >> 6;
    const int x     = pix & 63;

    const float mt = g_mtarget[b];
    const float* p = img + b * NPIX;

    float accum = 0.f;
    float wsum  = 0.f;

    if (mt > 0.f) {
        for (int base = 0; base < NOFF_PAD; base += 32) {
            const int pk = g_offsets[base + lane];        // coalesced
            const int dy = (pk >> 8) - 63;
            const int dx = (pk & 255) - 63;
            const int ny = y + dy;
            const int nx = x + dx;
            float w = 0.f;
            if ((unsigned)ny < (unsigned)HH && (unsigned)nx < (unsigned)WW)
                w = p[(ny << 6) | nx];

            // inclusive warp scan of w (table order preserved by lane order)
            float s = w;
            #pragma unroll
            for (int o = 1; o < 32; o <<= 1) {
                float t = __shfl_up_sync(FULL, s, o);
                if (lane >= o) s += t;
            }
            const float prev = accum + (s - w);            // exclusive prefix
            const float take = fmaxf(fminf(w, mt - prev), 0.f);
            wsum += take * (float)(dy * dy + dx * dx);

            accum += __shfl_sync(FULL, s, 31);             // chunk total
            if (accum >= mt) break;                        // warp-uniform
        }
    }

    // reduce wsum across warp
    #pragma unroll
    for (int o = 16; o; o >>= 1) wsum += __shfl_xor_sync(FULL, wsum, o);

    if (lane == 0) out[gwarp] = (mt > 0.f) ? sqrtf(wsum / mt) : 0.f;
}

// ---------------------------------------------------------------------------
extern "C" void kernel_launch(void* const* d_in, const int* in_sizes, int n_in,
                              void* d_out, int out_size) {
    const float* img = (const float*)d_in[0];
    float*       out = (float*)d_out;

    build_kernel<<<1, 1024>>>(img);
    dtm_kernel<<<(NB * NPIX * 32) / 256, 256>>>(img, out);   // 2048 blocks x 8 warps
}

// round 7
// speedup vs baseline: 4.8496x; 1.9699x over previous
#include <cuda_runtime.h>

// ExactWeightedDTM: B=4, H=W=64, N=4096, R=2, M0=0.01
//
// Identities (validated: rel_err ~1e-7):
//  - R=2 => dists_pow == d2 (integer 0..7938).
//  - Sort order is pure geometry => bake the d2-sorted offset table into the
//    binary at COMPILE TIME (constexpr counting sort).
//  - Tie order within equal d2 is irrelevant.
//  - Clamped take = max(min(w, mt - prefix), 0) over d2-nondecreasing order
//    reproduces the reference clamped-cumsum exactly; processing offsets past
//    the stopping point is harmless (take clamps to 0).

#define NB        4
#define HH        64
#define WW        64
#define NPIX      4096
#define NBINS     8192
#define NOFF      16129                // 127*127 offsets
#define NOFF_PAD  16160                // multiple of 32
#define TBL_SZ    16192                // +32 so prefetch never reads OOB
#define M0F       0.01f
#define FULL      0xFFFFFFFFu

// ---------------------------------------------------------------------------
// Compile-time d2-sorted offset table.
// Entry: (d2 << 16) | ((dy+63) << 8) | (dx+63).  Pad entries decode dy=+64
// (always out of bounds) with d2 = 0.
// ---------------------------------------------------------------------------
struct Table { unsigned v[TBL_SZ]; };

constexpr Table make_table() {
    Table t{};
    int cnt[NBINS] = {};
    for (int dy = -63; dy <= 63; dy++)
        for (int dx = -63; dx <= 63; dx++)
            cnt[dy * dy + dx * dx]++;
    int pos[NBINS] = {};
    int run = 0;
    for (int b = 0; b < NBINS; b++) { pos[b] = run; run += cnt[b]; }
    for (int dy = -63; dy <= 63; dy++)
        for (int dx = -63; dx <= 63; dx++) {
            int d2 = dy * dy + dx * dx;
            t.v[pos[d2]++] = ((unsigned)d2 << 16)
                           | ((unsigned)(dy + 63) << 8)
                           | (unsigned)(dx + 63);
        }
    for (int i = NOFF; i < TBL_SZ; i++) t.v[i] = 0x7F7Fu;  // dy=+64 -> OOB
    return t;
}

__device__ constexpr Table g_table = make_table();

// ---------------------------------------------------------------------------
// Single fused kernel. Block = 8 warps = 8 pixels of ONE batch.
//  1) stage the batch's 16KB image into smem (float4), summing on the fly
//  2) block-reduce -> m_target (each block computes it redundantly; cheaper
//     than a separate kernel launch)
//  3) one warp per pixel walks the d2-sorted table, 32 offsets per step via
//     an inclusive warp scan; next chunk's table entry + gather are
//     prefetched before the dependent shfl chain.
// ---------------------------------------------------------------------------
__global__ __launch_bounds__(256) void dtm_kernel(const float* __restrict__ img,
                                                  float* __restrict__ out) {
    __shared__ float s_img[NPIX];      // 16 KB
    __shared__ float s_red[8];
    __shared__ float s_mt;

    const int tid  = threadIdx.x;
    const int lane = tid & 31;
    const int wib  = tid >> 5;                       // warp in block, 0..7
    const int b    = blockIdx.x >> 9;                // 512 blocks per batch
    const int pix  = ((blockIdx.x & 511) << 3) + wib;
    const int y    = pix >> 6;
    const int x    = pix & 63;

    // ---- stage image + accumulate mass ----
    const float4* src = (const float4*)(img + b * NPIX);
    float4*       dst = (float4*)s_img;
    float sum = 0.f;
    #pragma unroll
    for (int i = 0; i < 4; i++) {
        float4 t = src[tid + i * 256];
        dst[tid + i * 256] = t;
        sum += (t.x + t.y) + (t.z + t.w);
    }
    #pragma unroll
    for (int o = 16; o; o >>= 1) sum += __shfl_xor_sync(FULL, sum, o);
    if (lane == 0) s_red[wib] = sum;
    __syncthreads();
    if (tid < 32) {
        float v = (tid < 8) ? s_red[tid] : 0.f;
        #pragma unroll
        for (int o = 4; o; o >>= 1) v += __shfl_xor_sync(FULL, v, o);
        if (tid == 0) s_mt = M0F * v;
    }
    __syncthreads();
    const float mt = s_mt;

    float accum = 0.f;
    float wsum  = 0.f;

    if (mt > 0.f) {
        // pipeline prologue: chunk 0
        unsigned v = g_table.v[lane];
        int dy = (int)((v >> 8) & 255) - 63;
        int dx = (int)(v & 255) - 63;
        int ny = y + dy, nx = x + dx;
        float w   = ((unsigned)ny < 64u && (unsigned)nx < 64u)
                        ? s_img[(ny << 6) | nx] : 0.f;
        float d2f = (float)(v >> 16);

        for (int base = 0; base < NOFF_PAD; base += 32) {
            // prefetch chunk base+32 (table is padded; smem gather is safe)
            unsigned v2 = g_table.v[base + 32 + lane];
            int dy2 = (int)((v2 >> 8) & 255) - 63;
            int dx2 = (int)(v2 & 255) - 63;
            int ny2 = y + dy2, nx2 = x + dx2;
            float w2   = ((unsigned)ny2 < 64u && (unsigned)nx2 < 64u)
                             ? s_img[(ny2 << 6) | nx2] : 0.f;
            float d2f2 = (float)(v2 >> 16);

            // inclusive warp scan of current chunk's weights
            float s = w;
            #pragma unroll
            for (int o = 1; o < 32; o <<= 1) {
                float t = __shfl_up_sync(FULL, s, o);
                if (lane >= o) s += t;
            }
            const float prev = accum + (s - w);               // exclusive prefix
            const float take = fmaxf(fminf(w, mt - prev), 0.f);
            wsum += take * d2f;

            accum += __shfl_sync(FULL, s, 31);                // chunk total
            if (accum >= mt) break;                           // warp-uniform

            w = w2; d2f = d2f2;
        }
    }

    // warp reduce wsum
    #pragma unroll
    for (int o = 16; o; o >>= 1) wsum += __shfl_xor_sync(FULL, wsum, o);

    if (lane == 0)
        out[b * NPIX + pix] = (mt > 0.f) ? sqrtf(wsum / mt) : 0.f;
}

// ---------------------------------------------------------------------------
extern "C" void kernel_launch(void* const* d_in, const int* in_sizes, int n_in,
                              void* d_out, int out_size) {
    const float* img = (const float*)d_in[0];
    float*       out = (float*)d_out;

    dtm_kernel<<<2048, 256>>>(img, out);   // 4 batches x 512 blocks x 8 pixels
}

// round 8
// speedup vs baseline: 5.6250x; 1.1599x over previous
#include <cuda_runtime.h>

// ExactWeightedDTM: B=4, H=W=64, N=4096, R=2, M0=0.01
//
// Identities (validated: rel_err ~1e-7):
//  - R=2 => dists_pow == d2 (integer 0..7938).
//  - Sort order is pure geometry => compile-time counting sort.
//  - Tie order within equal d2 is irrelevant.
//  - take = max(min(w, mt - prefix), 0) over d2-nondecreasing order matches
//    the reference clamped cumsum exactly; offsets past the stop contribute 0.

#define NB        4
#define NPIX      4096
#define NBINS     8192
#define NOFF      16129                // 127*127
#define NOFF_PAD  16192                // multiple of 64
#define TBL_SZ    16256                // +64 for prefetch overrun
#define M0F       0.01f
#define FULL      0xFFFFFFFFu

// ---------------------------------------------------------------------------
// Compile-time d2-sorted offset table: (d2<<16) | ((dy+63)<<8) | (dx+63).
// Pad entries decode dy=+64 -> always OOB, d2 ignored (w=0).
// ---------------------------------------------------------------------------
struct Table { unsigned v[TBL_SZ]; };

constexpr Table make_table() {
    Table t{};
    int cnt[NBINS] = {};
    for (int dy = -63; dy <= 63; dy++)
        for (int dx = -63; dx <= 63; dx++)
            cnt[dy * dy + dx * dx]++;
    int pos[NBINS] = {};
    int run = 0;
    for (int b = 0; b < NBINS; b++) { pos[b] = run; run += cnt[b]; }
    for (int dy = -63; dy <= 63; dy++)
        for (int dx = -63; dx <= 63; dx++) {
            int d2 = dy * dy + dx * dx;
            t.v[pos[d2]++] = ((unsigned)d2 << 16)
                           | ((unsigned)(dy + 63) << 8)
                           | (unsigned)(dx + 63);
        }
    for (int i = NOFF; i < TBL_SZ; i++) t.v[i] = 0x7F7Fu;
    return t;
}

__device__ constexpr Table g_table = make_table();

// decode one table entry against pixel (y,x); returns weight via smem gather
__device__ __forceinline__ void decode(unsigned v, int y, int x,
                                       const float* s_img, float& w, float& d2f) {
    int dy = (int)((v >> 8) & 255) - 63;
    int dx = (int)(v & 255) - 63;
    int ny = y + dy, nx = x + dx;
    w   = ((unsigned)ny < 64u && (unsigned)nx < 64u) ? s_img[(ny << 6) | nx] : 0.f;
    d2f = (float)(v >> 16);
}

// ---------------------------------------------------------------------------
// One fused kernel. Block = 16 warps = 16 pixels of ONE batch, pixels
// interleaved across the image (bid + wib*256) for load balance.
// Walk consumes 64 offsets/iteration via TWO interleaved warp scans (ILP=2).
// ---------------------------------------------------------------------------
__global__ __launch_bounds__(512) void dtm_kernel(const float* __restrict__ img,
                                                  float* __restrict__ out) {
    __shared__ float s_img[NPIX];      // 16 KB
    __shared__ float s_red[16];
    __shared__ float s_mt;

    const int tid  = threadIdx.x;
    const int lane = tid & 31;
    const int wib  = tid >> 5;                        // 0..15
    const int b    = blockIdx.x >> 8;                 // 256 blocks per batch
    const int pix  = (blockIdx.x & 255) + (wib << 8); // interleaved
    const int y    = pix >> 6;
    const int x    = pix & 63;

    // ---- stage image (float4) + accumulate mass on the fly ----
    const float4* src = (const float4*)(img + b * NPIX);
    float4*       dst = (float4*)s_img;
    float sum = 0.f;
    #pragma unroll
    for (int i = 0; i < 2; i++) {
        float4 t = src[tid + i * 512];
        dst[tid + i * 512] = t;
        sum += (t.x + t.y) + (t.z + t.w);
    }
    #pragma unroll
    for (int o = 16; o; o >>= 1) sum += __shfl_xor_sync(FULL, sum, o);
    if (lane == 0) s_red[wib] = sum;
    __syncthreads();
    if (tid < 32) {
        float v = (tid < 16) ? s_red[tid] : 0.f;
        #pragma unroll
        for (int o = 8; o; o >>= 1) v += __shfl_xor_sync(FULL, v, o);
        if (tid == 0) s_mt = M0F * v;
    }
    __syncthreads();
    const float mt = s_mt;

    float accum = 0.f;
    float wsum  = 0.f;

    if (mt > 0.f) {
        // prologue: first pair of chunks
        float w0, w1, d20, d21;
        decode(g_table.v[lane],      y, x, s_img, w0, d20);
        decode(g_table.v[32 + lane], y, x, s_img, w1, d21);

        for (int base = 0; base < NOFF_PAD; base += 64) {
            // prefetch next pair (table padded; safe)
            float w0n, w1n, d20n, d21n;
            decode(g_table.v[base + 64 + lane], y, x, s_img, w0n, d20n);
            decode(g_table.v[base + 96 + lane], y, x, s_img, w1n, d21n);

            // two interleaved inclusive warp scans (independent chains)
            float s0 = w0, s1 = w1;
            #pragma unroll
            for (int o = 1; o < 32; o <<= 1) {
                float t0 = __shfl_up_sync(FULL, s0, o);
                float t1 = __shfl_up_sync(FULL, s1, o);
                if (lane >= o) { s0 += t0; s1 += t1; }
            }
            const float T0 = __shfl_sync(FULL, s0, 31);
            const float T1 = __shfl_sync(FULL, s1, 31);

            const float prev0 = accum + (s0 - w0);
            const float take0 = fmaxf(fminf(w0, mt - prev0), 0.f);
            const float prev1 = accum + T0 + (s1 - w1);
            const float take1 = fmaxf(fminf(w1, mt - prev1), 0.f);
            wsum += take0 * d20 + take1 * d21;

            accum += T0 + T1;
            if (accum >= mt) break;                    // warp-uniform

            w0 = w0n; w1 = w1n; d20 = d20n; d21 = d21n;
        }
    }

    // warp reduce wsum
    #pragma unroll
    for (int o = 16; o; o >>= 1) wsum += __shfl_xor_sync(FULL, wsum, o);

    if (lane == 0)
        out[b * NPIX + pix] = (mt > 0.f) ? sqrtf(wsum / mt) : 0.f;
}

// ---------------------------------------------------------------------------
extern "C" void kernel_launch(void* const* d_in, const int* in_sizes, int n_in,
                              void* d_out, int out_size) {
    const float* img = (const float*)d_in[0];
    float*       out = (float*)d_out;

    dtm_kernel<<<1024, 512>>>(img, out);   // 4 batches x 256 blocks x 16 pixels
}

// round 11
// speedup vs baseline: 5.7761x; 1.0269x over previous
#include <cuda_runtime.h>

// ExactWeightedDTM: B=4, H=W=64, N=4096, R=2, M0=0.01
//
// Identities (validated: rel_err ~1e-7):
//  - R=2 => dists_pow == d2 (integer 0..7938).
//  - Sort order is pure geometry => compile-time counting sort.
//  - Tie order within equal d2 is irrelevant.
//  - take = max(min(w, mt - prefix), 0) over d2-nondecreasing order matches
//    the reference clamped cumsum exactly; offsets past the stop contribute 0.
//
// R9 structure: SINGLE WAVE. 256 blocks x 512 threads; block = one batch
// column x, 16 warps x 4 pixels each (rows wib, wib+16, wib+32, wib+48).
// No wave transitions, 4x less staging/mass redundancy, no speculative
// prefetch (most warps break after 1-2 iterations).

#define NB        4
#define NPIX      4096
#define NBINS     8192
#define NOFF      16129                // 127*127
#define NOFF_PAD  16192                // multiple of 64
#define TBL_SZ    16192
#define M0F       0.01f
#define FULL      0xFFFFFFFFu

// ---------------------------------------------------------------------------
// Compile-time d2-sorted offset table: (d2<<16) | ((dy+63)<<8) | (dx+63).
// Pad entries decode dy=+64 -> always OOB (w=0).
// ---------------------------------------------------------------------------
struct Table { unsigned v[TBL_SZ]; };

constexpr Table make_table() {
    Table t{};
    int cnt[NBINS] = {};
    for (int dy = -63; dy <= 63; dy++)
        for (int dx = -63; dx <= 63; dx++)
            cnt[dy * dy + dx * dx]++;
    int pos[NBINS] = {};
    int run = 0;
    for (int b = 0; b < NBINS; b++) { pos[b] = run; run += cnt[b]; }
    for (int dy = -63; dy <= 63; dy++)
        for (int dx = -63; dx <= 63; dx++) {
            int d2 = dy * dy + dx * dx;
            t.v[pos[d2]++] = ((unsigned)d2 << 16)
                           | ((unsigned)(dy + 63) << 8)
                           | (unsigned)(dx + 63);
        }
    for (int i = NOFF; i < TBL_SZ; i++) t.v[i] = 0x7F7Fu;
    return t;
}

__device__ constexpr Table g_table = make_table();

__device__ __forceinline__ void decode(unsigned v, int y, int x,
                                       const float* s_img, float& w, float& d2f) {
    int dy = (int)((v >> 8) & 255) - 63;
    int dx = (int)(v & 255) - 63;
    int ny = y + dy, nx = x + dx;
    w   = ((unsigned)ny < 64u && (unsigned)nx < 64u) ? s_img[(ny << 6) | nx] : 0.f;
    d2f = (float)(v >> 16);
}

// ---------------------------------------------------------------------------
__global__ __launch_bounds__(512) void dtm_kernel(const float* __restrict__ img,
                                                  float* __restrict__ out) {
    __shared__ float s_img[NPIX];      // 16 KB
    __shared__ float s_red[16];
    __shared__ float s_mt;

    const int tid  = threadIdx.x;
    const int lane = tid & 31;
    const int wib  = tid >> 5;                 // 0..15
    const int b    = blockIdx.x >> 6;          // 64 blocks per batch
    const int x    = blockIdx.x & 63;          // block column

    // ---- stage image (float4) + accumulate mass on the fly ----
    const float4* src = (const float4*)(img + b * NPIX);
    float4*       dst = (float4*)s_img;
    float sum = 0.f;
    #pragma unroll
    for (int i = 0; i < 2; i++) {
        float4 t = src[tid + i * 512];
        dst[tid + i * 512] = t;
        sum += (t.x + t.y) + (t.z + t.w);
    }
    #pragma unroll
    for (int o = 16; o; o >>= 1) sum += __shfl_xor_sync(FULL, sum, o);
    if (lane == 0) s_red[wib] = sum;
    __syncthreads();
    if (tid < 32) {
        float v = (tid < 16) ? s_red[tid] : 0.f;
        #pragma unroll
        for (int o = 8; o; o >>= 1) v += __shfl_xor_sync(FULL, v, o);
        if (tid == 0) s_mt = M0F * v;
    }
    __syncthreads();
    const float mt = s_mt;

    // ---- 4 pixels per warp: rows wib, wib+16, wib+32, wib+48, column x ----
    #pragma unroll
    for (int j = 0; j < 4; j++) {
        const int y   = wib + (j << 4);
        const int pix = (y << 6) | x;

        float accum = 0.f;
        float wsum  = 0.f;

        if (mt > 0.f) {
            for (int base = 0; base < NOFF_PAD; base += 64) {
                // load + decode chunk pair (independent -> overlapped)
                float w0, w1, d20, d21;
                decode(g_table.v[base + lane],      y, x, s_img, w0, d20);
                decode(g_table.v[base + 32 + lane], y, x, s_img, w1, d21);

                // two interleaved inclusive warp scans
                float s0 = w0, s1 = w1;
                #pragma unroll
                for (int o = 1; o < 32; o <<= 1) {
                    float t0 = __shfl_up_sync(FULL, s0, o);
                    float t1 = __shfl_up_sync(FULL, s1, o);
                    if (lane >= o) { s0 += t0; s1 += t1; }
                }
                const float T0 = __shfl_sync(FULL, s0, 31);
                const float T1 = __shfl_sync(FULL, s1, 31);

                const float prev0 = accum + (s0 - w0);
                const float take0 = fmaxf(fminf(w0, mt - prev0), 0.f);
                const float prev1 = accum + T0 + (s1 - w1);
                const float take1 = fmaxf(fminf(w1, mt - prev1), 0.f);
                wsum += take0 * d20 + take1 * d21;

                accum += T0 + T1;
                if (accum >= mt) break;            // warp-uniform
            }
        }

        #pragma unroll
        for (int o = 16; o; o >>= 1) wsum += __shfl_xor_sync(FULL, wsum, o);

        if (lane == 0)
            out[b * NPIX + pix] = (mt > 0.f) ? sqrtf(wsum / mt) : 0.f;
    }
}

// ---------------------------------------------------------------------------
extern "C" void kernel_launch(void* const* d_in, const int* in_sizes, int n_in,
                              void* d_out, int out_size) {
    const float* img = (const float*)d_in[0];
    float*       out = (float*)d_out;

    dtm_kernel<<<256, 512>>>(img, out);   // 4 batches x 64 columns, single wave
}